// round 16
// baseline (speedup 1.0000x reference)
#include <cuda_runtime.h>
#include <cuda_bf16.h>
#include <math.h>
#include <stdint.h>

#define N_NODES 50000
#define N_EDGES 800000
#define E_TOT   (N_EDGES + N_NODES)
#define IN_F    256
#define G       128            // 2*HID, GAT layer width
#define HIDF    64
#define NGRAPH  32
#define NB      ((N_NODES + 255) / 256)    // 196 scan blocks

// ---------------- scratch (static device globals; no allocation) ------------
__device__ float g_h1[N_NODES * G];     // gemm output (h), fp32
__device__ __nv_bfloat16 g_h1b[N_NODES * G];  // bf16 copy for gather
__device__ float g_h2[N_NODES * G];     // layer output
__device__ float g_es[N_NODES];
__device__ float g_ed[N_NODES];
__device__ int   g_deg[N_NODES];
__device__ int   g_off[N_NODES + 1];
__device__ int   g_cur[N_NODES];
__device__ int   g_col[E_TOT];
__device__ int   g_bsum[256];
__device__ int   g_bpre[256];
__device__ float g_pool[NGRAPH * G];
__device__ float g_cnt[NGRAPH];
// pre-split transposed weights: Wt[n][k], bf16 hi/lo
__device__ __nv_bfloat16 g_w1t_hi[G * IN_F];
__device__ __nv_bfloat16 g_w1t_lo[G * IN_F];
__device__ __nv_bfloat16 g_w2t_hi[G * G];
__device__ __nv_bfloat16 g_w2t_lo[G * G];

// ---------------- helpers ---------------------------------------------------
__device__ __forceinline__ float selu_f(float x) {
    const float sc = 1.0507009873554805f;
    const float al = 1.6732632423543772f;
    return x > 0.f ? sc * x : sc * al * (expf(x) - 1.f);
}

__device__ __forceinline__ uint32_t smem_to_u32(const void* smem_ptr) {
    uint32_t addr;
    asm("{ .reg .u64 tmp; cvta.to.shared.u64 tmp, %1; cvt.u32.u64 %0, tmp; }"
        : "=r"(addr) : "l"(smem_ptr));
    return addr;
}

__device__ __forceinline__ void ldsm4(uint32_t* r, uint32_t addr) {
    asm volatile("ldmatrix.sync.aligned.m8n8.x4.shared.b16 {%0,%1,%2,%3}, [%4];"
        : "=r"(r[0]), "=r"(r[1]), "=r"(r[2]), "=r"(r[3]) : "r"(addr));
}

__device__ __forceinline__ void mma_bf16(float* c, const uint32_t* a, const uint32_t* b) {
    asm volatile(
        "mma.sync.aligned.m16n8k16.row.col.f32.bf16.bf16.f32 "
        "{%0,%1,%2,%3}, {%4,%5,%6,%7}, {%8,%9}, {%0,%1,%2,%3};"
        : "+f"(c[0]), "+f"(c[1]), "+f"(c[2]), "+f"(c[3])
        : "r"(a[0]), "r"(a[1]), "r"(a[2]), "r"(a[3]), "r"(b[0]), "r"(b[1]));
}

__device__ __forceinline__ uint32_t pack_hi(float x, float y) {
    __nv_bfloat162 p = __halves2bfloat162(__float2bfloat16(x), __float2bfloat16(y));
    return *reinterpret_cast<uint32_t*>(&p);
}
__device__ __forceinline__ uint32_t pack_lo(float x, float y) {
    float hx = __bfloat162float(__float2bfloat16(x));
    float hy = __bfloat162float(__float2bfloat16(y));
    __nv_bfloat162 p = __halves2bfloat162(__float2bfloat16(x - hx), __float2bfloat16(y - hy));
    return *reinterpret_cast<uint32_t*>(&p);
}

// ---------------- weight transpose + hi/lo split (once per launch) ----------
__global__ void wsplit(const float* __restrict__ W1, const float* __restrict__ W2) {
    int i = blockIdx.x * blockDim.x + threadIdx.x;
    if (i < G * IN_F) {                          // W1t: n in 0..127, k in 0..255
        int n = i >> 8, k = i & 255;
        float v = W1[k * G + n];
        __nv_bfloat16 h = __float2bfloat16(v);
        g_w1t_hi[i] = h;
        g_w1t_lo[i] = __float2bfloat16(v - __bfloat162float(h));
    } else {
        int j = i - G * IN_F;                    // W2t: n, k in 0..127
        if (j < G * G) {
            int n = j >> 7, k = j & 127;
            float v = W2[k * G + n];
            __nv_bfloat16 h = __float2bfloat16(v);
            g_w2t_hi[j] = h;
            g_w2t_lo[j] = __float2bfloat16(v - __bfloat162float(h));
        }
    }
}

// ---------------- HMMA GEMM + fused attention terms --------------------------
#define TSTR 72                        // smem tile stride in bf16 (144 B = 9*16B)
#define SM_A_HI 0
#define SM_A_LO 18432
#define SM_B_HI 36864
#define SM_B_LO 55296
#define SM_RED  73728                  // float sEs[128][2], sEd[128][2]
#define SMEM_GEMM 75776

template<int K, int SRC_X>
__global__ void __launch_bounds__(256, 2)
gemm_mma(const float* __restrict__ Aparam,
         const float* __restrict__ asrc, const float* __restrict__ adst) {
    extern __shared__ __align__(1024) char smem[];
    const float* A = SRC_X ? Aparam : (const float*)g_h2;
    const __nv_bfloat16* wt_hi = SRC_X ? g_w1t_hi : g_w2t_hi;
    const __nv_bfloat16* wt_lo = SRC_X ? g_w1t_lo : g_w2t_lo;
    float* C = g_h1;

    int t    = threadIdx.x;
    int lane = t & 31;
    int wid  = t >> 5;
    int wm   = wid >> 1;
    int wn   = wid & 1;
    int base = blockIdx.x * 128;
    uint32_t sb = smem_to_u32(smem);

    float acc[2][8][4];
#pragma unroll
    for (int tm = 0; tm < 2; tm++)
#pragma unroll
        for (int tn = 0; tn < 8; tn++)
#pragma unroll
            for (int q = 0; q < 4; q++) acc[tm][tn][q] = 0.f;

    uint32_t a_off = (uint32_t)((wm * 32 + (lane & 15)) * (TSTR * 2) + ((lane >> 4) << 4));
    uint32_t b_off = (uint32_t)((wn * 64 + (lane & 7) + ((lane >> 4) << 3)) * (TSTR * 2)
                                + (((lane >> 3) & 1) << 4));

    constexpr int NCHUNK = K / 64;
    for (int ch = 0; ch < NCHUNK; ch++) {
        int k0 = ch * 64;
#pragma unroll
        for (int i = 0; i < 8; i++) {
            int idx = t + i * 256;
            int r   = idx >> 4;
            int c4  = (idx & 15) << 2;
            int row = base + r;
            float4 v = make_float4(0.f, 0.f, 0.f, 0.f);
            if (row < N_NODES)
                v = *reinterpret_cast<const float4*>(A + (size_t)row * K + k0 + c4);
            uint2 hp = make_uint2(pack_hi(v.x, v.y), pack_hi(v.z, v.w));
            uint2 lp = make_uint2(pack_lo(v.x, v.y), pack_lo(v.z, v.w));
            uint32_t bo = (uint32_t)(r * (TSTR * 2) + c4 * 2);
            *reinterpret_cast<uint2*>(smem + SM_A_HI + bo) = hp;
            *reinterpret_cast<uint2*>(smem + SM_A_LO + bo) = lp;
        }
#pragma unroll
        for (int i = 0; i < 8; i++) {
            int idx = t + i * 256;
            int n   = idx >> 4;
            int c4  = (idx & 15) << 2;
            uint2 hv = *reinterpret_cast<const uint2*>(wt_hi + (size_t)n * K + k0 + c4);
            uint2 lv = *reinterpret_cast<const uint2*>(wt_lo + (size_t)n * K + k0 + c4);
            uint32_t bo = (uint32_t)(n * (TSTR * 2) + c4 * 2);
            *reinterpret_cast<uint2*>(smem + SM_B_HI + bo) = hv;
            *reinterpret_cast<uint2*>(smem + SM_B_LO + bo) = lv;
        }
        __syncthreads();

#pragma unroll
        for (int ks = 0; ks < 4; ks++) {
            uint32_t kb = (uint32_t)(ks * 32);
            uint32_t ahi[2][4], alo[2][4];
#pragma unroll
            for (int tm = 0; tm < 2; tm++) {
                uint32_t ao = a_off + (uint32_t)(tm * 16 * TSTR * 2) + kb;
                ldsm4(ahi[tm], sb + SM_A_HI + ao);
                ldsm4(alo[tm], sb + SM_A_LO + ao);
            }
#pragma unroll
            for (int tg = 0; tg < 4; tg++) {
                uint32_t bo = b_off + (uint32_t)(tg * 16 * TSTR * 2) + kb;
                uint32_t bhi[4], blo[4];
                ldsm4(bhi, sb + SM_B_HI + bo);
                ldsm4(blo, sb + SM_B_LO + bo);
#pragma unroll
                for (int half = 0; half < 2; half++) {
                    int tn = tg * 2 + half;
#pragma unroll
                    for (int tm = 0; tm < 2; tm++) {
                        mma_bf16(acc[tm][tn], ahi[tm], &bhi[half * 2]);
                        mma_bf16(acc[tm][tn], ahi[tm], &blo[half * 2]);
                        mma_bf16(acc[tm][tn], alo[tm], &bhi[half * 2]);
                    }
                }
            }
        }
        __syncthreads();
    }

    float* sEs = reinterpret_cast<float*>(smem + SM_RED);
    float* sEd = sEs + 256;

    float asv0[8], asv1[8], adv0[8], adv1[8];
#pragma unroll
    for (int tn = 0; tn < 8; tn++) {
        int col = wn * 64 + tn * 8 + ((lane & 3) << 1);
        asv0[tn] = asrc[col]; asv1[tn] = asrc[col + 1];
        adv0[tn] = adst[col]; adv1[tn] = adst[col + 1];
    }
#pragma unroll
    for (int tm = 0; tm < 2; tm++) {
        int row0 = base + wm * 32 + tm * 16 + (lane >> 2);
#pragma unroll
        for (int h = 0; h < 2; h++) {
            int row = row0 + h * 8;
            float es = 0.f, ed = 0.f;
#pragma unroll
            for (int tn = 0; tn < 8; tn++) {
                float c0 = acc[tm][tn][h * 2], c1 = acc[tm][tn][h * 2 + 1];
                es += c0 * asv0[tn] + c1 * asv1[tn];
                ed += c0 * adv0[tn] + c1 * adv1[tn];
            }
            es += __shfl_xor_sync(0xffffffffu, es, 1);
            es += __shfl_xor_sync(0xffffffffu, es, 2);
            ed += __shfl_xor_sync(0xffffffffu, ed, 1);
            ed += __shfl_xor_sync(0xffffffffu, ed, 2);
            if ((lane & 3) == 0) {
                int rl = wm * 32 + tm * 16 + (lane >> 2) + h * 8;
                sEs[rl * 2 + wn] = es;
                sEd[rl * 2 + wn] = ed;
            }
            if (row < N_NODES) {
#pragma unroll
                for (int tn = 0; tn < 8; tn++) {
                    int col = wn * 64 + tn * 8 + ((lane & 3) << 1);
                    float2 v = make_float2(acc[tm][tn][h * 2], acc[tm][tn][h * 2 + 1]);
                    *reinterpret_cast<float2*>(C + (size_t)row * G + col) = v;
                    // bf16 copy for the aggregation gather (halves its traffic)
                    __nv_bfloat162 bv = __halves2bfloat162(__float2bfloat16(v.x),
                                                           __float2bfloat16(v.y));
                    *reinterpret_cast<__nv_bfloat162*>(g_h1b + (size_t)row * G + col) = bv;
                }
            }
        }
    }
    __syncthreads();
    if (t < 128) {
        int row = base + t;
        if (row < N_NODES) {
            g_es[row] = sEs[t * 2] + sEs[t * 2 + 1];
            g_ed[row] = sEd[t * 2] + sEd[t * 2 + 1];
        }
    }
}

// ---------------- CSR build ---------------------------------------------------
__global__ void zero_init() {
    int i = blockIdx.x * blockDim.x + threadIdx.x;
    if (i < N_NODES) g_deg[i] = 0;
    if (i < NGRAPH * G) g_pool[i] = 0.f;
    if (i < NGRAPH) g_cnt[i] = 0.f;
}

__global__ void hist_kernel(const int* __restrict__ ei) {
    int i = blockIdx.x * blockDim.x + threadIdx.x;
    if (i >= E_TOT) return;
    int d = (i < N_EDGES) ? ei[N_EDGES + i] : (i - N_EDGES);
    atomicAdd(&g_deg[d], 1);
}

__global__ void scanA() {
    __shared__ int sred[256];
    int t = threadIdx.x;
    int i = blockIdx.x * 256 + t;
    int v = (i < N_NODES) ? g_deg[i] : 0;
    sred[t] = v;
    __syncthreads();
#pragma unroll
    for (int o = 128; o > 0; o >>= 1) {
        if (t < o) sred[t] += sred[t + o];
        __syncthreads();
    }
    if (t == 0) g_bsum[blockIdx.x] = sred[0];
}

__global__ void scanB() {
    __shared__ int s[256];
    int t = threadIdx.x;
    int v = (t < NB) ? g_bsum[t] : 0;
    s[t] = v;
    __syncthreads();
#pragma unroll
    for (int o = 1; o < 256; o <<= 1) {
        int u = (t >= o) ? s[t - o] : 0;
        __syncthreads();
        s[t] += u;
        __syncthreads();
    }
    if (t < NB) g_bpre[t] = s[t] - v;
}

__global__ void scanC() {
    __shared__ int s[256];
    int t = threadIdx.x;
    int i = blockIdx.x * 256 + t;
    int v = (i < N_NODES) ? g_deg[i] : 0;
    s[t] = v;
    __syncthreads();
#pragma unroll
    for (int o = 1; o < 256; o <<= 1) {
        int u = (t >= o) ? s[t - o] : 0;
        __syncthreads();
        s[t] += u;
        __syncthreads();
    }
    if (i < N_NODES) {
        int excl = s[t] - v + g_bpre[blockIdx.x];
        g_off[i] = excl;
        g_cur[i] = excl;
        if (i == N_NODES - 1) g_off[N_NODES] = excl + v;
    }
}

__global__ void fill_kernel(const int* __restrict__ ei) {
    int i = blockIdx.x * blockDim.x + threadIdx.x;
    if (i >= E_TOT) return;
    int s, d;
    if (i < N_EDGES) { s = ei[i]; d = ei[N_EDGES + i]; }
    else             { s = i - N_EDGES; d = s; }
    int pos = atomicAdd(&g_cur[d], 1);
    g_col[pos] = s;
}

// ---------------- single-pass softmax aggregation + bias + SELU --------------
// messages gathered from bf16 copy (half traffic); logits/weights stay fp32
__global__ void agg_kernel(const float* __restrict__ bias) {
    int w    = (blockIdx.x * blockDim.x + threadIdx.x) >> 5;
    int lane = threadIdx.x & 31;
    if (w >= N_NODES) return;
    int beg = g_off[w], end = g_off[w + 1];
    float edd = g_ed[w];

    const __nv_bfloat16* h1b = (const __nv_bfloat16*)g_h1b;
    float4 acc = make_float4(0.f, 0.f, 0.f, 0.f);
    float den = 0.f;

    for (int j0 = beg; j0 < end; j0 += 32) {
        int j = j0 + lane;
        int s = 0; float wgt = 0.f;
        if (j < end) {
            s = g_col[j];
            float e = g_es[s] + edd;
            e = e > 0.f ? e : 0.2f * e;
            wgt = expf(e);
        }
        den += wgt;
        int cnt = min(32, end - j0);
        int tt = 0;
        for (; tt + 8 <= cnt; tt += 8) {
            int   si[8]; float ai[8];
#pragma unroll
            for (int q = 0; q < 8; q++) {
                si[q] = __shfl_sync(0xffffffffu, s, tt + q);
                ai[q] = __shfl_sync(0xffffffffu, wgt, tt + q);
            }
            uint2 hv[8];
#pragma unroll
            for (int q = 0; q < 8; q++)
                hv[q] = *reinterpret_cast<const uint2*>(h1b + (size_t)si[q] * G + lane * 4);
#pragma unroll
            for (int q = 0; q < 8; q++) {
                float2 f0 = __bfloat1622float2(*reinterpret_cast<__nv_bfloat162*>(&hv[q].x));
                float2 f1 = __bfloat1622float2(*reinterpret_cast<__nv_bfloat162*>(&hv[q].y));
                acc.x += ai[q] * f0.x; acc.y += ai[q] * f0.y;
                acc.z += ai[q] * f1.x; acc.w += ai[q] * f1.y;
            }
        }
        for (; tt + 4 <= cnt; tt += 4) {
            int   si[4]; float ai[4];
#pragma unroll
            for (int q = 0; q < 4; q++) {
                si[q] = __shfl_sync(0xffffffffu, s, tt + q);
                ai[q] = __shfl_sync(0xffffffffu, wgt, tt + q);
            }
            uint2 hv[4];
#pragma unroll
            for (int q = 0; q < 4; q++)
                hv[q] = *reinterpret_cast<const uint2*>(h1b + (size_t)si[q] * G + lane * 4);
#pragma unroll
            for (int q = 0; q < 4; q++) {
                float2 f0 = __bfloat1622float2(*reinterpret_cast<__nv_bfloat162*>(&hv[q].x));
                float2 f1 = __bfloat1622float2(*reinterpret_cast<__nv_bfloat162*>(&hv[q].y));
                acc.x += ai[q] * f0.x; acc.y += ai[q] * f0.y;
                acc.z += ai[q] * f1.x; acc.w += ai[q] * f1.y;
            }
        }
        for (; tt < cnt; tt++) {
            int   ss = __shfl_sync(0xffffffffu, s, tt);
            float a  = __shfl_sync(0xffffffffu, wgt, tt);
            uint2 hv = *reinterpret_cast<const uint2*>(h1b + (size_t)ss * G + lane * 4);
            float2 f0 = __bfloat1622float2(*reinterpret_cast<__nv_bfloat162*>(&hv.x));
            float2 f1 = __bfloat1622float2(*reinterpret_cast<__nv_bfloat162*>(&hv.y));
            acc.x += a * f0.x; acc.y += a * f0.y;
            acc.z += a * f1.x; acc.w += a * f1.y;
        }
    }
#pragma unroll
    for (int o = 16; o > 0; o >>= 1)
        den += __shfl_xor_sync(0xffffffffu, den, o);
    float inv = 1.f / (den + 1e-16f);

    float4 bv = *reinterpret_cast<const float4*>(bias + lane * 4);
    float4 o;
    o.x = selu_f(acc.x * inv + bv.x);
    o.y = selu_f(acc.y * inv + bv.y);
    o.z = selu_f(acc.z * inv + bv.z);
    o.w = selu_f(acc.w * inv + bv.w);
    *reinterpret_cast<float4*>(g_h2 + (size_t)w * G + lane * 4) = o;
}

// ---------------- pooling + head --------------------------------------------
#define POOL_CHUNK 256
__global__ void pool_kernel(const int* __restrict__ batch) {
    __shared__ float sp[NGRAPH * G];
    __shared__ float sc[NGRAPH];
    int j = threadIdx.x;
    for (int i = j; i < NGRAPH * G; i += 128) sp[i] = 0.f;
    if (j < NGRAPH) sc[j] = 0.f;
    __syncthreads();
    int start = blockIdx.x * POOL_CHUNK;
    int end   = min(start + POOL_CHUNK, N_NODES);
    for (int n = start; n < end; n++) {
        int b = batch[n];
        sp[b * G + j] += g_h2[(size_t)n * G + j];
        if (j == 0) sc[b] += 1.f;
    }
    __syncthreads();
    for (int i = j; i < NGRAPH * G; i += 128) atomicAdd(&g_pool[i], sp[i]);
    if (j < NGRAPH) atomicAdd(&g_cnt[j], sc[j]);
}

__global__ void mlp_kernel(const float* __restrict__ lw1, const float* __restrict__ lb1,
                           const float* __restrict__ lw2, const float* __restrict__ lb2,
                           float* __restrict__ out) {
    __shared__ float p[NGRAPH * G];
    __shared__ float z1[NGRAPH * HIDF];
    __shared__ float z2[NGRAPH * 2];
    int t = threadIdx.x;
    for (int i = t; i < NGRAPH * G; i += 128) {
        float c = g_cnt[i >> 7];
        p[i] = selu_f(g_pool[i] / fmaxf(c, 1.f));
    }
    __syncthreads();
    for (int o = t; o < NGRAPH * HIDF; o += 128) {
        int gi = o / HIDF, jj = o % HIDF;
        float s = lb1[jj];
        for (int k = 0; k < G; k++) s += p[gi * G + k] * lw1[k * HIDF + jj];
        z1[o] = selu_f(s);
    }
    __syncthreads();
    if (t < NGRAPH * 2) {
        int gi = t >> 1, c = t & 1;
        float s = lb2[c];
        for (int k = 0; k < HIDF; k++) s += z1[gi * HIDF + k] * lw2[k * 2 + c];
        z2[t] = s;
    }
    __syncthreads();
    if (t < NGRAPH * 2) {
        int gi = t >> 1;
        float a = z2[gi * 2], b = z2[gi * 2 + 1];
        float mx = fmaxf(a, b);
        float lse = mx + logf(expf(a - mx) + expf(b - mx));
        out[t] = z2[t] - lse;
    }
}

// ---------------- launch -----------------------------------------------------
extern "C" void kernel_launch(void* const* d_in, const int* in_sizes, int n_in,
                              void* d_out, int out_size) {
    const float* x     = (const float*)d_in[0];
    const int*   ei    = (const int*)d_in[1];
    const int*   batch = (const int*)d_in[2];
    const float* W1    = (const float*)d_in[3];
    const float* as1   = (const float*)d_in[4];
    const float* ad1   = (const float*)d_in[5];
    const float* b1    = (const float*)d_in[6];
    const float* W2    = (const float*)d_in[7];
    const float* as2   = (const float*)d_in[8];
    const float* ad2   = (const float*)d_in[9];
    const float* b2    = (const float*)d_in[10];
    const float* lw1   = (const float*)d_in[11];
    const float* lb1   = (const float*)d_in[12];
    const float* lw2   = (const float*)d_in[13];
    const float* lb2   = (const float*)d_in[14];
    float*       out   = (float*)d_out;

    cudaFuncSetAttribute(gemm_mma<IN_F, 1>, cudaFuncAttributeMaxDynamicSharedMemorySize, SMEM_GEMM);
    cudaFuncSetAttribute(gemm_mma<G, 0>,    cudaFuncAttributeMaxDynamicSharedMemorySize, SMEM_GEMM);

    const int gemm_blocks = (N_NODES + 127) / 128;
    const int node_warps  = (N_NODES * 32 + 255) / 256;
    const int node_blocks = (N_NODES + 255) / 256;
    const int edge_blocks = (E_TOT + 255) / 256;

    // Fork a side stream so the CSR build overlaps wsplit+gemm1.
    cudaStream_t s2;
    cudaEvent_t evFork, evJoin;
    cudaStreamCreateWithFlags(&s2, cudaStreamNonBlocking);
    cudaEventCreateWithFlags(&evFork, cudaEventDisableTiming);
    cudaEventCreateWithFlags(&evJoin, cudaEventDisableTiming);

    cudaEventRecord(evFork, 0);
    cudaStreamWaitEvent(s2, evFork, 0);

    // ---- side stream: CSR build ----
    zero_init<<<node_blocks, 256, 0, s2>>>();
    hist_kernel<<<edge_blocks, 256, 0, s2>>>(ei);
    scanA<<<NB, 256, 0, s2>>>();
    scanB<<<1, 256, 0, s2>>>();
    scanC<<<NB, 256, 0, s2>>>();
    fill_kernel<<<edge_blocks, 256, 0, s2>>>(ei);
    cudaEventRecord(evJoin, s2);

    // ---- main stream: weight split + layer-1 GEMM (independent of CSR) ----
    wsplit<<<(G * IN_F + G * G + 255) / 256, 256>>>(W1, W2);
    gemm_mma<IN_F, 1><<<gemm_blocks, 256, SMEM_GEMM>>>(x, as1, ad1);

    // join: aggregation needs both the CSR and h1/es/ed
    cudaStreamWaitEvent(0, evJoin, 0);

    // ---- layer 1 aggregation ----
    agg_kernel<<<node_warps, 256>>>(b1);

    // ---- layer 2 ----
    gemm_mma<G, 0><<<gemm_blocks, 256, SMEM_GEMM>>>(nullptr, as2, ad2);
    agg_kernel<<<node_warps, 256>>>(b2);

    // ---- pooling + MLP head ----
    pool_kernel<<<(N_NODES + POOL_CHUNK - 1) / POOL_CHUNK, 128>>>(batch);
    mlp_kernel<<<1, 128>>>(lw1, lb1, lw2, lb2, out);
}